// round 4
// baseline (speedup 1.0000x reference)
#include <cuda_runtime.h>
#include <cuda_bf16.h>

// Problem constants (fixed by the dataset): B=4096 rows, C=8192 classes, K=8 positives.
#define NB 4096
#define NC 8192
#define NK 8
#define THREADS 256
#define PER_THREAD (NC / THREADS)   // 32 floats per thread
#define NVEC (PER_THREAD / 4)       // 8 float4 loads per thread
#define NWARPS (THREADS / 32)

// Grid-level accumulator (no cudaMalloc allowed).
__device__ double g_accum;

__global__ void mls_zero_kernel() { g_accum = 0.0; }

__global__ __launch_bounds__(THREADS) void mls_row_kernel(
    const float* __restrict__ pred,
    const int*   __restrict__ labels)
{
    const int b = blockIdx.x;
    const int t = threadIdx.x;
    const float4* __restrict__ row =
        reinterpret_cast<const float4*>(pred + (size_t)b * NC);

    // ---- one coalesced pass: 8x LDG.128 per thread, front-batched ----
    float4 v[NVEC];
#pragma unroll
    for (int i = 0; i < NVEC; i++) v[i] = row[t + i * THREADS];

    // ---- local max ----
    float m = -1e30f;
#pragma unroll
    for (int i = 0; i < NVEC; i++) {
        m = fmaxf(m, fmaxf(fmaxf(v[i].x, v[i].y), fmaxf(v[i].z, v[i].w)));
    }
    // warp reduce
#pragma unroll
    for (int off = 16; off; off >>= 1)
        m = fmaxf(m, __shfl_xor_sync(0xFFFFFFFFu, m, off));

    __shared__ float smax[NWARPS];
    __shared__ float ssum[NWARPS];
    const int warp = t >> 5, lane = t & 31;
    if (lane == 0) smax[warp] = m;
    __syncthreads();

    float M = smax[0];
#pragma unroll
    for (int w = 1; w < NWARPS; w++) M = fmaxf(M, smax[w]);

    // ---- sum of exp(x - M) over ALL classes (positives subtracted later) ----
    float s = 0.f;
#pragma unroll
    for (int i = 0; i < NVEC; i++) {
        s += __expf(v[i].x - M) + __expf(v[i].y - M)
           + __expf(v[i].z - M) + __expf(v[i].w - M);
    }
#pragma unroll
    for (int off = 16; off; off >>= 1)
        s += __shfl_xor_sync(0xFFFFFFFFu, s, off);
    if (lane == 0) ssum[warp] = s;
    __syncthreads();

    if (t == 0) {
        float S = 0.f;
#pragma unroll
        for (int w = 0; w < NWARPS; w++) S += ssum[w];

        const int* __restrict__ lab = labels + b * NK;
        float pos[NK];
        float pos_exp = 0.f;
#pragma unroll
        for (int k = 0; k < NK; k++) {
            pos[k] = __ldg(pred + (size_t)b * NC + lab[k]);
            pos_exp += __expf(pos[k] - M);
        }
        // logsumexp over negatives only (8184 of them -> S - pos_exp is
        // comfortably positive; rel tolerance is 1e-3 so fast-math is fine)
        const float lse_neg = M + __logf(S - pos_exp);

        float acc = 0.f;
#pragma unroll
        for (int k = 0; k < NK; k++) {
            // logaddexp(pos, lse_neg) - pos = log1p(exp(lse_neg - pos))
            acc += log1pf(__expf(lse_neg - pos[k]));
        }
        atomicAdd(&g_accum, (double)acc);
    }
}

__global__ void mls_finalize_kernel(float* __restrict__ out) {
    out[0] = (float)(g_accum / (double)((long long)NB * NK));
}

extern "C" void kernel_launch(void* const* d_in, const int* in_sizes, int n_in,
                              void* d_out, int out_size) {
    const float* pred   = (const float*)d_in[0];   // [B, C] float32
    const int*   labels = (const int*)d_in[1];     // [B, K] int32
    float* out = (float*)d_out;                    // scalar float32

    mls_zero_kernel<<<1, 1>>>();
    mls_row_kernel<<<NB, THREADS>>>(pred, labels);
    mls_finalize_kernel<<<1, 1>>>(out);
}

// round 5
// speedup vs baseline: 1.0234x; 1.0234x over previous
#include <cuda_runtime.h>
#include <cuda_bf16.h>

// Problem constants (fixed by the dataset): B=4096 rows, C=8192 classes, K=8 positives.
#define NB 4096
#define NC 8192
#define NK 8
#define THREADS 256
#define PER_THREAD (NC / THREADS)   // 32 floats per thread
#define NVEC (PER_THREAD / 4)       // 8 float4 loads per thread
#define NWARPS (THREADS / 32)

// Grid-level state (no cudaMalloc allowed). Self-resetting: every kernel run
// leaves these back at their initial values, so graph replays are deterministic.
__device__ double       g_accum = 0.0;
__device__ unsigned int g_count = 0u;

__global__ __launch_bounds__(THREADS) void mls_fused_kernel(
    const float* __restrict__ pred,
    const int*   __restrict__ labels,
    float*       __restrict__ out)
{
    const int b = blockIdx.x;
    const int t = threadIdx.x;
    const float* __restrict__ rowp = pred + (size_t)b * NC;
    const float4* __restrict__ row = reinterpret_cast<const float4*>(rowp);

    __shared__ float smax[NWARPS];
    __shared__ float ssum[NWARPS];
    __shared__ float spos[NK];

    // ---- overlap: lanes 0..7 gather the positive logits early (L2/L1 hits
    //      on the same row this block is streaming) ----
    if (t < NK) spos[t] = __ldg(rowp + __ldg(labels + b * NK + t));

    // ---- one coalesced pass: 8x LDG.128 per thread, front-batched ----
    float4 v[NVEC];
#pragma unroll
    for (int i = 0; i < NVEC; i++) v[i] = row[t + i * THREADS];

    // ---- local + warp + block max ----
    float m = -1e30f;
#pragma unroll
    for (int i = 0; i < NVEC; i++)
        m = fmaxf(m, fmaxf(fmaxf(v[i].x, v[i].y), fmaxf(v[i].z, v[i].w)));
#pragma unroll
    for (int off = 16; off; off >>= 1)
        m = fmaxf(m, __shfl_xor_sync(0xFFFFFFFFu, m, off));

    const int warp = t >> 5, lane = t & 31;
    if (lane == 0) smax[warp] = m;
    __syncthreads();

    float M = smax[0];
#pragma unroll
    for (int w = 1; w < NWARPS; w++) M = fmaxf(M, smax[w]);

    // ---- sum of exp(x - M) over ALL classes (positives subtracted later) ----
    float s = 0.f;
#pragma unroll
    for (int i = 0; i < NVEC; i++) {
        s += __expf(v[i].x - M) + __expf(v[i].y - M)
           + __expf(v[i].z - M) + __expf(v[i].w - M);
    }
#pragma unroll
    for (int off = 16; off; off >>= 1)
        s += __shfl_xor_sync(0xFFFFFFFFu, s, off);
    if (lane == 0) ssum[warp] = s;
    __syncthreads();

    if (t == 0) {
        float S = 0.f;
#pragma unroll
        for (int w = 0; w < NWARPS; w++) S += ssum[w];

        float pos_exp = 0.f;
#pragma unroll
        for (int k = 0; k < NK; k++) pos_exp += __expf(spos[k] - M);

        // logsumexp over negatives only (8184 of them -> S - pos_exp stays
        // comfortably positive; rel tolerance is 1e-3 so fast-math is fine)
        const float lse_neg = M + __logf(S - pos_exp);

        float acc = 0.f;
#pragma unroll
        for (int k = 0; k < NK; k++) {
            // logaddexp(pos, lse_neg) - pos = log1p(exp(lse_neg - pos))
            acc += log1pf(__expf(lse_neg - spos[k]));
        }
        atomicAdd(&g_accum, (double)acc);

        // ---- grid finalize: last block writes output and resets state ----
        __threadfence();
        unsigned ticket = atomicAdd(&g_count, 1u);
        if (ticket == NB - 1) {
            // atomicExch reads the full total and resets g_accum to 0.0
            unsigned long long bits =
                atomicExch(reinterpret_cast<unsigned long long*>(&g_accum), 0ULL);
            double total = __longlong_as_double(bits);
            out[0] = (float)(total / (double)((long long)NB * NK));
            g_count = 0u;   // visible at kernel boundary before next replay
        }
    }
}

extern "C" void kernel_launch(void* const* d_in, const int* in_sizes, int n_in,
                              void* d_out, int out_size) {
    const float* pred   = (const float*)d_in[0];   // [B, C] float32
    const int*   labels = (const int*)d_in[1];     // [B, K] int32
    float* out = (float*)d_out;                    // scalar float32

    mls_fused_kernel<<<NB, THREADS>>>(pred, labels, out);
}